// round 13
// baseline (speedup 1.0000x reference)
#include <cuda_runtime.h>
#include <math.h>
#include <stdint.h>

#define N_ROWS 8192
#define DIM    128

#define NT 56            // rows per block -> 147 blocks (one per SM)
#define KC 32            // i-chunk staged in smem
#define NCH (DIM / KC)   // 4 chunks
#define THREADS 512      // 32 col-threads x 16 warps
#define OR 4             // cols per thread (2 packed pairs)
#define XSTR 36          // padded float stride for raw x rows
#define RSTR 58          // padded float2 stride for transformed rows [i][n]
#define NBLOCKS ((N_ROWS + NT - 1) / NT)   // 147

// ---- weight planes (prep kernel output); scalar planes so adjacent o-cols
//      load directly as packed u64 FFMA2 operands ----
__device__ float gGa[DIM * DIM];   // g (clipped)
__device__ float gWy[DIM * DIM];   // ln2*Wr
__device__ float gWz[DIM * DIM];   // ln2*Wi
__device__ float gP [DIM * DIM];   // -pi*g*Wi
__device__ float gQ [DIM * DIM];   // pi*g*Wr

__global__ void NPU_prep_kernel(const float* __restrict__ Wr,
                                const float* __restrict__ Wi,
                                const float* __restrict__ G) {
    int idx = blockIdx.x * blockDim.x + threadIdx.x;
    if (idx >= DIM * DIM) return;
    float g = fminf(fmaxf(G[idx], 0.0f), 1.0f);
    float wr = Wr[idx];
    float wi = Wi[idx];
    const float LN2 = 0.69314718055994530942f;
    const float PI  = 3.14159265358979323846f;
    gGa[idx] = g;
    gWy[idx] = LN2 * wr;
    gWz[idx] = LN2 * wi;
    gP [idx] = -PI * g * wi;
    gQ [idx] = PI * g * wr;
}

// ---- smem: two stages ----
#define SG_OFF    0
#define SWY_OFF   (KC * DIM * 4)                   // 16384
#define SWZ_OFF   (SWY_OFF + KC * DIM * 4)         // 32768
#define SP_OFF    (SWZ_OFF + KC * DIM * 4)         // 49152
#define SQ_OFF    (SP_OFF  + KC * DIM * 4)         // 65536
#define SXRAW_OFF (SQ_OFF  + KC * DIM * 4)         // 81920
#define SROW_OFF  (SXRAW_OFF + ((NT * XSTR * 4 + 127) & ~127))  // 81920+8064->8064 pad
#define STG_BYTES (((SROW_OFF + KC * RSTR * 8) + 127) & ~127)
#define SMEM_TOTAL (2 * STG_BYTES)

#define FMA_F32X2(d, a, b) \
    asm("fma.rn.f32x2 %0, %1, %2, %0;" : "+l"(d) : "l"(a), "l"(b))
#define PACK_DUP(d, s) \
    asm("mov.b64 %0, {%1, %1};" : "=l"(d) : "r"(s))
#define PACK2(d, lo, hi) \
    asm("mov.b64 %0, {%1, %2};" : "=l"(d) : "r"(lo), "r"(hi))

__device__ __forceinline__ void cp16(uint32_t dst, const void* src) {
    asm volatile("cp.async.cg.shared.global [%0], [%1], 16;"
                 :: "r"(dst), "l"(src));
}

__device__ __forceinline__ void stage_chunk(const float* __restrict__ x,
                                            int i0, uint32_t st,
                                            int n0, int tid) {
    #pragma unroll
    for (int k = tid; k < KC * DIM / 4; k += THREADS) {   // 1024 per plane
        int ir = k >> 5, o4 = (k & 31) * 4;
        uint32_t off = (uint32_t)(ir * DIM + o4) * 4;
        int src = (i0 + ir) * DIM + o4;
        cp16(st + SG_OFF  + off, &gGa[src]);
        cp16(st + SWY_OFF + off, &gWy[src]);
        cp16(st + SWZ_OFF + off, &gWz[src]);
        cp16(st + SP_OFF  + off, &gP [src]);
        cp16(st + SQ_OFF  + off, &gQ [src]);
    }
    if (tid < NT * KC / 4) {                              // x: 448 cp16
        int n  = tid >> 3;            // 0..55
        int s4 = (tid & 7) * 4;       // 0..28
        int ng = n0 + n;
        if (ng >= N_ROWS) ng = N_ROWS - 1;   // clamp (stores guarded later)
        cp16(st + SXRAW_OFF + (uint32_t)(n * XSTR + s4) * 4,
             &x[ng * DIM + i0 + s4]);
    }
}

// Warp-local transform: warp w converts its NRA rows into sRow[i][n]=(am1,nf).
template<int NRA>
__device__ __forceinline__ void xform_rows(const float* __restrict__ sXraw,
                                           float2* __restrict__ sRow,
                                           int w, int lane) {
    #pragma unroll
    for (int r = 0; r < NRA; r++) {
        int row = w + 16 * r;
        float xr = sXraw[row * XSTR + lane];       // lane = i index, conflict-free
        float am1 = (fabsf(xr) + 1e-36f) - 1.0f;
        float nf  = xr < 0.0f ? 1.0f : 0.0f;
        sRow[lane * RSTR + row] = make_float2(am1, nf);
    }
    __syncwarp();
}

// Hot loop over one KC-chunk for NRA rows (col-pair packed accumulators).
template<int NRA>
__device__ __forceinline__ void hot_chunk(const float* __restrict__ sG,
                                          const float* __restrict__ sWy,
                                          const float* __restrict__ sWz,
                                          const float* __restrict__ sP,
                                          const float* __restrict__ sQ,
                                          const float2* __restrict__ sRow,
                                          int oc, int w,
                                          unsigned long long (&A)[4][2],
                                          unsigned long long (&B)[4][2]) {
    #pragma unroll 2
    for (int i = 0; i < KC; i++) {
        float4 gv = *(const float4*)&sG[i * DIM + oc];
        ulonglong2 wy = *(const ulonglong2*)&sWy[i * DIM + oc];
        ulonglong2 wz = *(const ulonglong2*)&sWz[i * DIM + oc];
        ulonglong2 pp = *(const ulonglong2*)&sP [i * DIM + oc];
        ulonglong2 qq = *(const ulonglong2*)&sQ [i * DIM + oc];
        unsigned long long wy2[2] = {wy.x, wy.y};
        unsigned long long wz2[2] = {wz.x, wz.y};
        unsigned long long pj2[2] = {pp.x, pp.y};
        unsigned long long qj2[2] = {qq.x, qq.y};
        float gj[OR] = {gv.x, gv.y, gv.z, gv.w};

        float am1[NRA];
        unsigned long long nfnf[NRA];
        #pragma unroll
        for (int r = 0; r < NRA; r++) {
            float2 rv = sRow[i * RSTR + w + 16 * r];   // warp-broadcast
            am1[r] = rv.x;
            PACK_DUP(nfnf[r], __float_as_uint(rv.y));
        }

        #pragma unroll
        for (int r = 0; r < NRA; r++) {
            #pragma unroll
            for (int p = 0; p < 2; p++) {
                float R0 = fmaf(am1[r], gj[2*p+0], 1.0f);
                float R1 = fmaf(am1[r], gj[2*p+1], 1.0f);
                float t0 = __log2f(R0);                 // MUFU.LG2
                float t1 = __log2f(R1);
                unsigned long long tt;
                PACK2(tt, __float_as_uint(t0), __float_as_uint(t1));
                FMA_F32X2(A[r][p], tt, wy2[p]);          // A-pair += t2*wy2
                FMA_F32X2(B[r][p], tt, wz2[p]);          // B-pair += t2*wz2
                FMA_F32X2(A[r][p], nfnf[r], pj2[p]);     // A-pair += nf*p2
                FMA_F32X2(B[r][p], nfnf[r], qj2[p]);     // B-pair += nf*q2
            }
        }
    }
}

__global__ __launch_bounds__(THREADS, 1)
void NPU_main_kernel(const float* __restrict__ x, float* __restrict__ out) {
    extern __shared__ char smem[];
    const uint32_t sbase = (uint32_t)__cvta_generic_to_shared(smem);

    const int tid  = threadIdx.x;
    const int lane = tid & 31;
    const int n0   = blockIdx.x * NT;
    const int oc   = (tid & 31) * OR;    // col offset (0..124)
    const int w    = tid >> 5;           // warp id = row-group (0..15)
    const bool four_rows = (w < 8);      // warps 0-7: 4 rows; 8-15: 3 rows

    unsigned long long A[4][2], B[4][2];
    #pragma unroll
    for (int r = 0; r < 4; r++)
        #pragma unroll
        for (int p = 0; p < 2; p++) { A[r][p] = 0ULL; B[r][p] = 0ULL; }

    stage_chunk(x, 0, sbase, n0, tid);
    asm volatile("cp.async.commit_group;");

    for (int c = 0; c < NCH; c++) {
        const int s = c & 1;
        if (c + 1 < NCH) {
            stage_chunk(x, (c + 1) * KC, sbase + (uint32_t)((s ^ 1) * STG_BYTES),
                        n0, tid);
            asm volatile("cp.async.commit_group;");
            asm volatile("cp.async.wait_group 1;");
        } else {
            asm volatile("cp.async.wait_group 0;");
        }
        __syncthreads();

        const char* stg = smem + s * STG_BYTES;
        const float*  sG    = (const float*) (stg + SG_OFF);
        const float*  sWy   = (const float*) (stg + SWY_OFF);
        const float*  sWz   = (const float*) (stg + SWZ_OFF);
        const float*  sP    = (const float*) (stg + SP_OFF);
        const float*  sQ    = (const float*) (stg + SQ_OFF);
        const float*  sXraw = (const float*) (stg + SXRAW_OFF);
        float2*       sRow  = (float2*)      (stg + SROW_OFF);

        if (four_rows) {
            xform_rows<4>(sXraw, sRow, w, lane);
            hot_chunk<4>(sG, sWy, sWz, sP, sQ, sRow, oc, w, A, B);
        } else {
            xform_rows<3>(sXraw, sRow, w, lane);
            hot_chunk<3>(sG, sWy, sWz, sP, sQ, sRow, oc, w, A, B);
        }
        __syncthreads();
    }

    // ---- epilogue: out = exp(A) * cos(B) (fast MUFU paths) ----
    const int nra = four_rows ? 4 : 3;
    #pragma unroll
    for (int r = 0; r < 4; r++) {
        if (r >= nra) break;
        int ng = n0 + w + 16 * r;
        if (ng >= N_ROWS) continue;
        float av[OR], bv[OR];
        #pragma unroll
        for (int p = 0; p < 2; p++) {
            av[2*p+0] = __uint_as_float((unsigned int)(A[r][p] & 0xffffffffULL));
            av[2*p+1] = __uint_as_float((unsigned int)(A[r][p] >> 32));
            bv[2*p+0] = __uint_as_float((unsigned int)(B[r][p] & 0xffffffffULL));
            bv[2*p+1] = __uint_as_float((unsigned int)(B[r][p] >> 32));
        }
        float4 v;
        v.x = __expf(av[0]) * __cosf(bv[0]);
        v.y = __expf(av[1]) * __cosf(bv[1]);
        v.z = __expf(av[2]) * __cosf(bv[2]);
        v.w = __expf(av[3]) * __cosf(bv[3]);
        *(float4*)&out[ng * DIM + oc] = v;
    }
}

extern "C" void kernel_launch(void* const* d_in, const int* in_sizes, int n_in,
                              void* d_out, int out_size) {
    const float* x  = (const float*)d_in[0];
    const float* Wr = (const float*)d_in[1];
    const float* Wi = (const float*)d_in[2];
    const float* G  = (const float*)d_in[3];
    float* out = (float*)d_out;
    (void)in_sizes; (void)n_in; (void)out_size;

    NPU_prep_kernel<<<(DIM * DIM + 255) / 256, 256>>>(Wr, Wi, G);

    cudaFuncSetAttribute(NPU_main_kernel,
                         cudaFuncAttributeMaxDynamicSharedMemorySize, SMEM_TOTAL);
    NPU_main_kernel<<<NBLOCKS, THREADS, SMEM_TOTAL>>>(x, out);
}

// round 14
// speedup vs baseline: 1.0043x; 1.0043x over previous
#include <cuda_runtime.h>
#include <math.h>
#include <stdint.h>

#define N_ROWS 8192
#define DIM    128

#define NT 28            // rows per block -> 293 blocks = 2 per SM, single wave
#define KC 32            // i-chunk staged in smem
#define NCH (DIM / KC)   // 4 chunks
#define THREADS 256      // 32 col-threads x 8 warps
#define OR 4             // cols per thread (32*4 = 128 = full o)
#define XSTR 36          // padded float stride for raw x rows
#define NBLOCKS ((N_ROWS + NT - 1) / NT)   // 293

// ---- packed weights (prep kernel output) ----
__device__ float  gG  [DIM * DIM];
__device__ float2 gWyz[DIM * DIM];   // (ln2*Wr, ln2*Wi)
__device__ float2 gPQ [DIM * DIM];   // (-pi*g*Wi, pi*g*Wr)

__global__ void NPU_prep_kernel(const float* __restrict__ Wr,
                                const float* __restrict__ Wi,
                                const float* __restrict__ G) {
    int idx = blockIdx.x * blockDim.x + threadIdx.x;
    if (idx >= DIM * DIM) return;
    float g = fminf(fmaxf(G[idx], 0.0f), 1.0f);
    float wr = Wr[idx];
    float wi = Wi[idx];
    const float LN2 = 0.69314718055994530942f;
    const float PI  = 3.14159265358979323846f;
    gG[idx]   = g;
    gWyz[idx] = make_float2(LN2 * wr, LN2 * wi);
    gPQ[idx]  = make_float2(-PI * g * wi, PI * g * wr);
}

// ---- smem per block: single-stage weights + double-buffered raw x ----
#define SG_OFF    0
#define SWYZ_OFF  (KC * DIM * 4)                   // 16384
#define SPQ_OFF   (SWYZ_OFF + KC * DIM * 8)        // 49152
#define SX_OFF    (SPQ_OFF + KC * DIM * 8)         // 81920
#define SX_BYTES  ((NT * XSTR * 4 + 127) & ~127)   // 4096
#define SMEM_TOTAL (SX_OFF + 2 * SX_BYTES)         // 90112 -> 2 blocks/SM

#define FMA_F32X2(d, a, b) \
    asm("fma.rn.f32x2 %0, %1, %2, %0;" : "+l"(d) : "l"(a), "l"(b))
#define PACK_DUP(d, s) \
    asm("mov.b64 %0, {%1, %1};" : "=l"(d) : "r"(s))

__device__ __forceinline__ void cp16(uint32_t dst, const void* src) {
    asm volatile("cp.async.cg.shared.global [%0], [%1], 16;"
                 :: "r"(dst), "l"(src));
}

__device__ __forceinline__ void stage_weights(int i0, uint32_t st, int tid) {
    #pragma unroll
    for (int k = tid; k < KC * DIM / 4; k += THREADS) {   // g: 1024 cp16
        int ir = k >> 5, o4 = (k & 31) * 4;
        cp16(st + SG_OFF + (uint32_t)(ir * DIM + o4) * 4,
             &gG[(i0 + ir) * DIM + o4]);
    }
    #pragma unroll
    for (int k = tid; k < KC * DIM / 2; k += THREADS) {   // wyz,pq: 2048 each
        int ir = k >> 6, o2 = (k & 63) * 2;
        cp16(st + SWYZ_OFF + (uint32_t)(ir * DIM + o2) * 8,
             &gWyz[(i0 + ir) * DIM + o2]);
        cp16(st + SPQ_OFF + (uint32_t)(ir * DIM + o2) * 8,
             &gPQ[(i0 + ir) * DIM + o2]);
    }
}

__device__ __forceinline__ void stage_x(const float* __restrict__ x,
                                        int i0, uint32_t xs, int n0, int tid) {
    if (tid < NT * KC / 4) {                              // 224 cp16
        int n  = tid >> 3;            // 0..27
        int s4 = (tid & 7) * 4;       // 0..28
        int ng = n0 + n;
        if (ng >= N_ROWS) ng = N_ROWS - 1;   // clamp (stores guarded later)
        cp16(xs + (uint32_t)(n * XSTR + s4) * 4,
             &x[ng * DIM + i0 + s4]);
    }
}

// Hot loop over one KC-chunk for NRA rows (warp-uniform; R11 codegen).
template<int NRA>
__device__ __forceinline__ void hot_chunk(const float* __restrict__ sG,
                                          const float2* __restrict__ sWyz,
                                          const float2* __restrict__ sPQ,
                                          const float* __restrict__ sX,
                                          int oc, int w,
                                          unsigned long long (&AB)[4][OR]) {
    #pragma unroll 2
    for (int i = 0; i < KC; i++) {
        float4 gv = *(const float4*)&sG[i * DIM + oc];
        ulonglong2 w01 = *(const ulonglong2*)&sWyz[i * DIM + oc];
        ulonglong2 w23 = *(const ulonglong2*)&sWyz[i * DIM + oc + 2];
        ulonglong2 p01 = *(const ulonglong2*)&sPQ [i * DIM + oc];
        ulonglong2 p23 = *(const ulonglong2*)&sPQ [i * DIM + oc + 2];
        unsigned long long wj[OR] = {w01.x, w01.y, w23.x, w23.y};
        unsigned long long pj[OR] = {p01.x, p01.y, p23.x, p23.y};
        float gj[OR] = {gv.x, gv.y, gv.z, gv.w};

        float am1[NRA];
        unsigned long long nfnf[NRA];
        #pragma unroll
        for (int r = 0; r < NRA; r++) {
            float xr = sX[(w + 8 * r) * XSTR + i];       // warp-broadcast
            am1[r] = (fabsf(xr) + 1e-36f) - 1.0f;
            float nf = xr < 0.0f ? 1.0f : 0.0f;
            PACK_DUP(nfnf[r], __float_as_uint(nf));
        }

        #pragma unroll
        for (int r = 0; r < NRA; r++) {
            #pragma unroll
            for (int j = 0; j < OR; j++) {
                float R = fmaf(am1[r], gj[j], 1.0f);     // a*g + (1-g)
                float t = __log2f(R);                     // MUFU.LG2
                unsigned long long tt;
                PACK_DUP(tt, __float_as_uint(t));
                FMA_F32X2(AB[r][j], tt, wj[j]);           // (A,B) += t*(wy,wz)
                FMA_F32X2(AB[r][j], nfnf[r], pj[j]);      // (A,B) += nf*(P,Q)
            }
        }
    }
}

__global__ __launch_bounds__(THREADS, 2)
void NPU_main_kernel(const float* __restrict__ x, float* __restrict__ out) {
    extern __shared__ char smem[];
    const uint32_t sbase = (uint32_t)__cvta_generic_to_shared(smem);

    const int tid = threadIdx.x;
    const int n0  = blockIdx.x * NT;
    const int oc  = (tid & 31) * OR;     // col offset (0..124)
    const int w   = tid >> 5;            // warp id = row-group (0..7)
    const bool four_rows = (w < 4);      // warps 0-3: rows w+8r, r<4; else r<3

    unsigned long long AB[4][OR];
    #pragma unroll
    for (int r = 0; r < 4; r++)
        #pragma unroll
        for (int j = 0; j < OR; j++) AB[r][j] = 0ULL;

    // prologue: weights(0) + x(0)
    stage_weights(0, sbase, tid);
    stage_x(x, 0, sbase + SX_OFF, n0, tid);
    asm volatile("cp.async.commit_group;");

    for (int c = 0; c < NCH; c++) {
        const int s = c & 1;
        asm volatile("cp.async.wait_group 0;");
        __syncthreads();                 // weights(c) + x(c) visible

        if (c + 1 < NCH) {               // prefetch x(c+1) (overlaps compute)
            stage_x(x, (c + 1) * KC,
                    sbase + SX_OFF + (uint32_t)((s ^ 1) * SX_BYTES), n0, tid);
            asm volatile("cp.async.commit_group;");
        }

        const float*  sG   = (const float*) (smem + SG_OFF);
        const float2* sWyz = (const float2*)(smem + SWYZ_OFF);
        const float2* sPQ  = (const float2*)(smem + SPQ_OFF);
        const float*  sX   = (const float*) (smem + SX_OFF + s * SX_BYTES);

        if (four_rows) hot_chunk<4>(sG, sWyz, sPQ, sX, oc, w, AB);
        else           hot_chunk<3>(sG, sWyz, sPQ, sX, oc, w, AB);

        __syncthreads();                 // all warps done with weights(c)

        if (c + 1 < NCH) {               // restage weights (sibling block covers stall)
            stage_weights((c + 1) * KC, sbase, tid);
            asm volatile("cp.async.commit_group;");
        }
    }

    // ---- epilogue: out = exp(A) * cos(B) (fast MUFU paths) ----
    const int nra = four_rows ? 4 : 3;
    #pragma unroll
    for (int r = 0; r < 4; r++) {
        if (r >= nra) break;
        int ng = n0 + w + 8 * r;
        if (ng >= N_ROWS) continue;
        float av[OR], bv[OR];
        #pragma unroll
        for (int j = 0; j < OR; j++) {
            av[j] = __uint_as_float((unsigned int)(AB[r][j] & 0xffffffffULL));
            bv[j] = __uint_as_float((unsigned int)(AB[r][j] >> 32));
        }
        float4 v;
        v.x = __expf(av[0]) * __cosf(bv[0]);
        v.y = __expf(av[1]) * __cosf(bv[1]);
        v.z = __expf(av[2]) * __cosf(bv[2]);
        v.w = __expf(av[3]) * __cosf(bv[3]);
        *(float4*)&out[ng * DIM + oc] = v;
    }
}

extern "C" void kernel_launch(void* const* d_in, const int* in_sizes, int n_in,
                              void* d_out, int out_size) {
    const float* x  = (const float*)d_in[0];
    const float* Wr = (const float*)d_in[1];
    const float* Wi = (const float*)d_in[2];
    const float* G  = (const float*)d_in[3];
    float* out = (float*)d_out;
    (void)in_sizes; (void)n_in; (void)out_size;

    NPU_prep_kernel<<<(DIM * DIM + 255) / 256, 256>>>(Wr, Wi, G);

    cudaFuncSetAttribute(NPU_main_kernel,
                         cudaFuncAttributeMaxDynamicSharedMemorySize, SMEM_TOTAL);
    NPU_main_kernel<<<NBLOCKS, THREADS, SMEM_TOTAL>>>(x, out);
}